// round 1
// baseline (speedup 1.0000x reference)
#include <cuda_runtime.h>
#include <math.h>

// Problem constants
#define NB   32      // batch
#define SL   256     // sequence length
#define DD   1024    // input dim
#define HH   1024    // hidden dim

// ---------------------------------------------------------------------------
// Scratch (device globals; no dynamic allocation allowed)
// ---------------------------------------------------------------------------
// Precomputed input projections: xh[g][s][n][h], g in [0,8)
__device__ float g_xh[(size_t)8 * SL * NB * HH];          // 268 MB
// Hidden state double buffer: [parity][dir][n][h]
__device__ float g_hbuf[2][2][NB][HH];
// Cell state: [dir][n][h]
__device__ float g_cbuf[2][NB][HH];

// ---------------------------------------------------------------------------
// Kernel 0: zero init of h and c
// ---------------------------------------------------------------------------
__global__ void zero_state_kernel() {
    int idx = blockIdx.x * blockDim.x + threadIdx.x;
    int total_h = 2 * 2 * NB * HH;
    int total_c = 2 * NB * HH;
    float* h = &g_hbuf[0][0][0][0];
    float* c = &g_cbuf[0][0][0];
    for (int i = idx; i < total_h; i += gridDim.x * blockDim.x) h[i] = 0.0f;
    for (int i = idx; i < total_c; i += gridDim.x * blockDim.x) c[i] = 0.0f;
}

// ---------------------------------------------------------------------------
// Kernel 1: input projection GEMM
//   xh[g][s][n][h] = sum_d x[n][s][d] * wih[g][d][h] + bias[g][h]
//   A = x viewed as [M=8192][K=1024] with row r = n*256 + s
//   B = wih[g] as [K=1024][N=1024]
// 128x128x8 tile, 256 threads, 8x8 per-thread micro-tile.
// ---------------------------------------------------------------------------
#define BM 128
#define BN 128
#define BK 8

__global__ __launch_bounds__(256, 2)
void gemm_ih_kernel(const float* __restrict__ x,
                    const float* __restrict__ wih,
                    const float* __restrict__ bias) {
    const int g  = blockIdx.z;
    const int m0 = blockIdx.x * BM;
    const int n0 = blockIdx.y * BN;

    __shared__ float As[BK][BM];
    __shared__ float Bs[BK][BN];

    const float* A = x;                                   // [8192][1024]
    const float* B = wih + (size_t)g * DD * HH;           // [1024][1024]

    const int tid = threadIdx.x;          // 0..255
    const int a_row = tid >> 1;           // 0..127
    const int a_k   = (tid & 1) * 4;      // 0 or 4
    const int b_k   = tid >> 5;           // 0..7
    const int b_n   = (tid & 31) * 4;     // 0..124

    const int tx = tid & 15;              // 0..15 -> n cols
    const int ty = tid >> 4;              // 0..15 -> m rows

    float acc[8][8];
#pragma unroll
    for (int i = 0; i < 8; i++)
#pragma unroll
        for (int j = 0; j < 8; j++) acc[i][j] = 0.0f;

    for (int k0 = 0; k0 < DD; k0 += BK) {
        // Load A tile (transposed into smem)
        float4 av = *(const float4*)(A + (size_t)(m0 + a_row) * DD + k0 + a_k);
        As[a_k + 0][a_row] = av.x;
        As[a_k + 1][a_row] = av.y;
        As[a_k + 2][a_row] = av.z;
        As[a_k + 3][a_row] = av.w;
        // Load B tile
        *(float4*)(&Bs[b_k][b_n]) =
            *(const float4*)(B + (size_t)(k0 + b_k) * HH + n0 + b_n);
        __syncthreads();

#pragma unroll
        for (int k = 0; k < BK; k++) {
            float a[8], b[8];
#pragma unroll
            for (int i = 0; i < 8; i++) a[i] = As[k][ty * 8 + i];
#pragma unroll
            for (int j = 0; j < 8; j++) b[j] = Bs[k][tx * 8 + j];
#pragma unroll
            for (int i = 0; i < 8; i++)
#pragma unroll
                for (int j = 0; j < 8; j++)
                    acc[i][j] = fmaf(a[i], b[j], acc[i][j]);
        }
        __syncthreads();
    }

    // Epilogue: scatter into xh[g][s][n][h] with bias
    const int col0 = n0 + tx * 8;
#pragma unroll
    for (int i = 0; i < 8; i++) {
        int row  = m0 + ty * 8 + i;      // r = n*256 + s
        int nidx = row >> 8;
        int s    = row & 255;
        size_t base = ((((size_t)g * SL + s) * NB + nidx) << 10) + col0;
#pragma unroll
        for (int j = 0; j < 8; j++) {
            g_xh[base + j] = acc[i][j] + bias[g * HH + col0 + j];
        }
    }
}

// ---------------------------------------------------------------------------
// Kernel 2: one BiLSTM time step (both directions), fused GEMM + pointwise.
// grid: (64 h-tiles of 16 cols, 2 dirs), 128 threads.
// Thread (tx=tid&3, ty=tid>>2): computes 4 gates x 4 h-cols for batch row ty.
// ---------------------------------------------------------------------------
__device__ __forceinline__ float sigmf(float v) {
    return 1.0f / (1.0f + expf(-v));
}

__global__ __launch_bounds__(128)
void lstm_step_kernel(const float* __restrict__ whh,
                      const float* __restrict__ mask,
                      float* __restrict__ out,
                      int t) {
    const int dir   = blockIdx.y;            // 0 fwd, 1 bwd
    const int htile = blockIdx.x;            // 0..63
    const int tid   = threadIdx.x;           // 0..127
    const int tx    = tid & 3;               // h quad within tile
    const int ty    = tid >> 2;              // batch row 0..31
    const int h0    = htile * 16 + tx * 4;
    const int gbase = dir * 4;
    const int pos   = (dir == 0) ? t : (SL - 1 - t);   // seq position
    const int rb    = t & 1;                 // h read-buffer parity

    __shared__ float sh_h[32][33];           // [kk][n], padded
    __shared__ float sh_w[4][32][16];        // [gate][kk][h]

    // Init accumulators from precomputed x-projection
    float acc[4][4];
#pragma unroll
    for (int g = 0; g < 4; g++) {
        float4 v = *(const float4*)&g_xh[
            ((((size_t)(gbase + g) * SL + pos) * NB + ty) << 10) + h0];
        acc[g][0] = v.x; acc[g][1] = v.y; acc[g][2] = v.z; acc[g][3] = v.w;
    }

    const float* hprev = &g_hbuf[rb][dir][0][0];   // [32][1024]

    for (int k0 = 0; k0 < HH; k0 += 32) {
        // Cooperative load: h_prev tile [32 k][32 n] (transposed)
        {
            int n  = tid >> 2;
            int kq = (tid & 3) * 8;
            float4 v0 = *(const float4*)(hprev + ((size_t)n << 10) + k0 + kq);
            float4 v1 = *(const float4*)(hprev + ((size_t)n << 10) + k0 + kq + 4);
            sh_h[kq + 0][n] = v0.x; sh_h[kq + 1][n] = v0.y;
            sh_h[kq + 2][n] = v0.z; sh_h[kq + 3][n] = v0.w;
            sh_h[kq + 4][n] = v1.x; sh_h[kq + 5][n] = v1.y;
            sh_h[kq + 6][n] = v1.z; sh_h[kq + 7][n] = v1.w;
        }
        // Cooperative load: weight tile [4 gates][32 k][16 h]
#pragma unroll
        for (int r = 0; r < 4; r++) {
            int i   = tid + r * 128;         // 0..511 float4 slots
            int g   = i >> 7;
            int rem = i & 127;
            int kk  = rem >> 2;
            int q   = (rem & 3) * 4;
            float4 v = *(const float4*)(whh +
                ((size_t)(gbase + g) << 20) + ((size_t)(k0 + kk) << 10) +
                htile * 16 + q);
            *(float4*)&sh_w[g][kk][q] = v;
        }
        __syncthreads();

#pragma unroll
        for (int kk = 0; kk < 32; kk++) {
            float hv = sh_h[kk][ty];
#pragma unroll
            for (int g = 0; g < 4; g++) {
                float4 w = *(const float4*)&sh_w[g][kk][tx * 4];
                acc[g][0] = fmaf(hv, w.x, acc[g][0]);
                acc[g][1] = fmaf(hv, w.y, acc[g][1]);
                acc[g][2] = fmaf(hv, w.z, acc[g][2]);
                acc[g][3] = fmaf(hv, w.w, acc[g][3]);
            }
        }
        __syncthreads();
    }

    // ---- Pointwise LSTM cell (thread-local) ----
    const float m = mask[ty * SL + pos];
    float4 c_old = *(const float4*)&g_cbuf[dir][ty][h0];
    float4 h_old = *(const float4*)&g_hbuf[rb][dir][ty][h0];

    float c_o[4] = {c_old.x, c_old.y, c_old.z, c_old.w};
    float h_o[4] = {h_old.x, h_old.y, h_old.z, h_old.w};
    float c_n[4], hid[4];

#pragma unroll
    for (int j = 0; j < 4; j++) {
        float f  = sigmf(acc[0][j]);
        float ii = sigmf(acc[1][j]);
        float o  = sigmf(acc[2][j]);
        float cb = tanhf(acc[3][j]);
        c_n[j] = f * c_o[j] + ii * cb;
        float hn = o * tanhf(c_n[j]);
        hid[j] = (m == 0.0f) ? h_o[j] : hn;
    }

    // Store new c and h (write parity = rb^1)
    *(float4*)&g_cbuf[dir][ty][h0] =
        make_float4(c_n[0], c_n[1], c_n[2], c_n[3]);
    *(float4*)&g_hbuf[rb ^ 1][dir][ty][h0] =
        make_float4(hid[0], hid[1], hid[2], hid[3]);

    // hidden_states output: out[n][pos][dir*H + h] = hid * mask
    {
        size_t base = (((size_t)ty * SL + pos) * 2 * HH) + (size_t)dir * HH + h0;
        *(float4*)&out[base] = make_float4(hid[0] * m, hid[1] * m,
                                           hid[2] * m, hid[3] * m);
    }
    // final_state at last scan step: fwd h at t=S-1, bwd h at t=S-1 (pos 0)
    if (t == SL - 1) {
        size_t fbase = (size_t)NB * SL * 2 * HH +
                       (size_t)ty * 2 * HH + (size_t)dir * HH + h0;
        *(float4*)&out[fbase] = make_float4(hid[0], hid[1], hid[2], hid[3]);
    }
}

// ---------------------------------------------------------------------------
// Launch
// ---------------------------------------------------------------------------
extern "C" void kernel_launch(void* const* d_in, const int* in_sizes, int n_in,
                              void* d_out, int out_size) {
    const float* x    = (const float*)d_in[0];   // (32,256,1024)
    const float* mask = (const float*)d_in[1];   // (32,256)
    const float* wih  = (const float*)d_in[2];   // (8,1024,1024)
    const float* whh  = (const float*)d_in[3];   // (8,1024,1024)
    const float* bias = (const float*)d_in[4];   // (8,1,1024)
    float* out = (float*)d_out;

    // Zero h/c state
    zero_state_kernel<<<192, 256>>>();

    // Input projection GEMM: grid (M/128=64, N/128=8, gates=8)
    dim3 ggrid(64, 8, 8);
    gemm_ih_kernel<<<ggrid, 256>>>(x, wih, bias);

    // Recurrence: 256 sequential step kernels
    dim3 sgrid(64, 2);
    for (int t = 0; t < SL; t++) {
        lstm_step_kernel<<<sgrid, 128>>>(whh, mask, out, t);
    }
}

// round 2
// speedup vs baseline: 2.2573x; 2.2573x over previous
#include <cuda_runtime.h>
#include <math.h>

// Problem constants
#define NB   32      // batch
#define SL   256     // sequence length
#define DD   1024    // input dim
#define HH   1024    // hidden dim
#define NKC  16      // k-chunks for split-K recurrence
#define KCH  (HH/NKC) // 64

// ---------------------------------------------------------------------------
// Scratch (device globals)
// ---------------------------------------------------------------------------
__device__ float g_xh[(size_t)8 * SL * NB * HH];          // 268 MB: xh[g][s][n][h]
__device__ float g_hbuf[2][2][NB][HH];                    // [parity][dir][n][h]
__device__ float g_cbuf[2][NB][HH];                       // [dir][n][h]
__device__ float g_part[2][NKC][NB][4 * HH];              // 16.8 MB split-K partials

typedef unsigned long long u64;

__device__ __forceinline__ u64 pk2(float x, float y) {
    u64 r; asm("mov.b64 %0, {%1,%2};" : "=l"(r) : "f"(x), "f"(y)); return r;
}
__device__ __forceinline__ void upk2(u64 v, float& x, float& y) {
    asm("mov.b64 {%0,%1}, %2;" : "=f"(x), "=f"(y) : "l"(v));
}
__device__ __forceinline__ void ffma2(u64& c, u64 a, u64 b) {
    asm("fma.rn.f32x2 %0, %1, %2, %0;" : "+l"(c) : "l"(a), "l"(b));
}
__device__ __forceinline__ float sigmf(float v) {
    return 1.0f / (1.0f + expf(-v));
}

// ---------------------------------------------------------------------------
// Kernel 0: zero init of h and c
// ---------------------------------------------------------------------------
__global__ void zero_state_kernel() {
    int idx = blockIdx.x * blockDim.x + threadIdx.x;
    int total_h = 2 * 2 * NB * HH;
    int total_c = 2 * NB * HH;
    float* h = &g_hbuf[0][0][0][0];
    float* c = &g_cbuf[0][0][0];
    for (int i = idx; i < total_h; i += gridDim.x * blockDim.x) h[i] = 0.0f;
    for (int i = idx; i < total_c; i += gridDim.x * blockDim.x) c[i] = 0.0f;
}

// ---------------------------------------------------------------------------
// Kernel 1: input projection GEMM (f32x2 packed FMA)
//   xh[g][s][n][h] = sum_d x[n][s][d] * wih[g][d][h] + bias[g][h]
// 128x128x8 tile, 256 threads, 8x8 micro-tile (rows paired into f32x2 lanes).
// ---------------------------------------------------------------------------
#define BM 128
#define BN 128
#define BK 8

__global__ __launch_bounds__(256, 2)
void gemm_ih_kernel(const float* __restrict__ x,
                    const float* __restrict__ wih,
                    const float* __restrict__ bias) {
    const int g  = blockIdx.z;
    const int m0 = blockIdx.x * BM;
    const int n0 = blockIdx.y * BN;

    __shared__ float As[BK][BM];
    __shared__ float Bs[BK][BN];

    const float* A = x;                                   // [8192][1024]
    const float* B = wih + (size_t)g * DD * HH;           // [1024][1024]

    const int tid = threadIdx.x;
    const int a_row = tid >> 1;
    const int a_k   = (tid & 1) * 4;
    const int b_k   = tid >> 5;
    const int b_n   = (tid & 31) * 4;

    const int tx = tid & 15;              // col group (8 cols)
    const int ty = tid >> 4;              // row group (8 rows = 4 pairs)

    u64 acc[4][8];
#pragma unroll
    for (int p = 0; p < 4; p++)
#pragma unroll
        for (int j = 0; j < 8; j++) acc[p][j] = pk2(0.0f, 0.0f);

    for (int k0 = 0; k0 < DD; k0 += BK) {
        float4 av = *(const float4*)(A + (size_t)(m0 + a_row) * DD + k0 + a_k);
        As[a_k + 0][a_row] = av.x;
        As[a_k + 1][a_row] = av.y;
        As[a_k + 2][a_row] = av.z;
        As[a_k + 3][a_row] = av.w;
        *(float4*)(&Bs[b_k][b_n]) =
            *(const float4*)(B + (size_t)(k0 + b_k) * HH + n0 + b_n);
        __syncthreads();

#pragma unroll
        for (int k = 0; k < BK; k++) {
            u64 ap[4];
#pragma unroll
            for (int p = 0; p < 4; p++)
                ap[p] = *(const u64*)&As[k][ty * 8 + 2 * p];
            float4 b0 = *(const float4*)&Bs[k][tx * 8];
            float4 b1 = *(const float4*)&Bs[k][tx * 8 + 4];
            u64 bb[8];
            bb[0] = pk2(b0.x, b0.x); bb[1] = pk2(b0.y, b0.y);
            bb[2] = pk2(b0.z, b0.z); bb[3] = pk2(b0.w, b0.w);
            bb[4] = pk2(b1.x, b1.x); bb[5] = pk2(b1.y, b1.y);
            bb[6] = pk2(b1.z, b1.z); bb[7] = pk2(b1.w, b1.w);
#pragma unroll
            for (int p = 0; p < 4; p++)
#pragma unroll
                for (int j = 0; j < 8; j++)
                    ffma2(acc[p][j], ap[p], bb[j]);
        }
        __syncthreads();
    }

    // Epilogue: scatter into xh[g][s][n][h] with bias
    const int col0 = n0 + tx * 8;
#pragma unroll
    for (int p = 0; p < 4; p++) {
        float lo[8], hi[8];
#pragma unroll
        for (int j = 0; j < 8; j++) upk2(acc[p][j], lo[j], hi[j]);
#pragma unroll
        for (int half = 0; half < 2; half++) {
            int row  = m0 + ty * 8 + 2 * p + half;    // r = n*256 + s
            int nidx = row >> 8;
            int s    = row & 255;
            size_t base = ((((size_t)g * SL + s) * NB + nidx) << 10) + col0;
            const float* v = half ? hi : lo;
#pragma unroll
            for (int j = 0; j < 8; j++)
                g_xh[base + j] = v[j] + bias[g * HH + col0 + j];
        }
    }
}

// ---------------------------------------------------------------------------
// Kernel 2: recurrence GEMM, split-K.
//   partial[dir][kc][n][col] = sum_{k in chunk kc} h_prev[n][k] * Whh[dir*4+g][k][h]
//   where col = g*1024 + h.  Tile: 32n x 256col, K-chunk 64.
// grid (16 htiles, 16 kchunks, 2 dirs) = 512 blocks, 128 threads.
// Micro-tile 8n x 8col as 4 row-pairs x 8 cols of f32x2.
// ---------------------------------------------------------------------------
__global__ __launch_bounds__(128)
void recur_gemm_kernel(const float* __restrict__ whh, int t) {
    const int ht  = blockIdx.x;            // 0..15
    const int kc  = blockIdx.y;            // 0..15
    const int dir = blockIdx.z;            // 0..1
    const int tid = threadIdx.x;           // 0..127
    const int col0 = ht * 256;
    const int gate = col0 >> 10;           // tile lies in a single gate
    const int hcol = col0 & 1023;
    const int rb   = t & 1;

    __shared__ float As[16][34];           // [k][n], padded to 8B-aligned rows
    __shared__ float Bs[16][256];          // [k][col]

    const float* hprev = &g_hbuf[rb][dir][0][0];             // [32][1024]
    const float* W = whh + (((size_t)(dir * 4 + gate)) << 20) + hcol;

    const int tr = tid >> 5;               // 0..3 -> rows tr*8..tr*8+7
    const int tc = tid & 31;               // 0..31 -> cols tc*8..tc*8+7

    const int an = tid & 31;               // h-tile load: batch row
    const int aq = (tid >> 5) * 4;         // h-tile load: k quad

    u64 acc[4][8];
#pragma unroll
    for (int p = 0; p < 4; p++)
#pragma unroll
        for (int j = 0; j < 8; j++) acc[p][j] = pk2(0.0f, 0.0f);

    for (int it = 0; it < KCH / 16; ++it) {      // 4 iterations of BK=16
        const int kb = kc * KCH + it * 16;

        // Stage global loads in registers (overlaps with previous compute)
        float4 hv = *(const float4*)(hprev + ((size_t)an << 10) + kb + aq);
        float4 wv[8];
#pragma unroll
        for (int r = 0; r < 8; ++r) {
            int lin = tid + r * 128;             // 0..1023 float4 slots
            int kk  = lin >> 6;
            int c4  = (lin & 63) * 4;
            wv[r] = *(const float4*)(W + (size_t)(kb + kk) * HH + c4);
        }
        __syncthreads();                          // prev-iter readers done

        As[aq + 0][an] = hv.x; As[aq + 1][an] = hv.y;
        As[aq + 2][an] = hv.z; As[aq + 3][an] = hv.w;
#pragma unroll
        for (int r = 0; r < 8; ++r) {
            int lin = tid + r * 128;
            *(float4*)&Bs[lin >> 6][(lin & 63) * 4] = wv[r];
        }
        __syncthreads();

#pragma unroll
        for (int kk = 0; kk < 16; ++kk) {
            u64 ap[4];
#pragma unroll
            for (int p = 0; p < 4; p++)
                ap[p] = *(const u64*)&As[kk][tr * 8 + 2 * p];   // broadcast in warp
            float4 b0 = *(const float4*)&Bs[kk][tc * 8];
            float4 b1 = *(const float4*)&Bs[kk][tc * 8 + 4];
            u64 bb[8];
            bb[0] = pk2(b0.x, b0.x); bb[1] = pk2(b0.y, b0.y);
            bb[2] = pk2(b0.z, b0.z); bb[3] = pk2(b0.w, b0.w);
            bb[4] = pk2(b1.x, b1.x); bb[5] = pk2(b1.y, b1.y);
            bb[6] = pk2(b1.z, b1.z); bb[7] = pk2(b1.w, b1.w);
#pragma unroll
            for (int p = 0; p < 4; p++)
#pragma unroll
                for (int j = 0; j < 8; j++)
                    ffma2(acc[p][j], ap[p], bb[j]);
        }
    }

    // Write partials: rows are batch n, cols are col0 + tc*8 + j
    float* P = &g_part[dir][kc][0][0];            // [32][4096]
#pragma unroll
    for (int p = 0; p < 4; p++) {
        float lo[8], hi[8];
#pragma unroll
        for (int j = 0; j < 8; j++) upk2(acc[p][j], lo[j], hi[j]);
        int r0 = tr * 8 + 2 * p;
        size_t base0 = (size_t)r0 * 4096 + col0 + tc * 8;
        size_t base1 = base0 + 4096;
        *(float4*)&P[base0]     = make_float4(lo[0], lo[1], lo[2], lo[3]);
        *(float4*)&P[base0 + 4] = make_float4(lo[4], lo[5], lo[6], lo[7]);
        *(float4*)&P[base1]     = make_float4(hi[0], hi[1], hi[2], hi[3]);
        *(float4*)&P[base1 + 4] = make_float4(hi[4], hi[5], hi[6], hi[7]);
    }
}

// ---------------------------------------------------------------------------
// Kernel 3: reduce partials + LSTM pointwise cell.
// 65536 threads: one per (dir, n, h).
// ---------------------------------------------------------------------------
__global__ __launch_bounds__(256)
void cell_kernel(const float* __restrict__ mask, float* __restrict__ out, int t) {
    const int idx = blockIdx.x * 256 + threadIdx.x;   // 0..65535
    const int h   = idx & 1023;
    const int n   = (idx >> 10) & 31;
    const int dir = idx >> 15;
    const int pos = dir ? (SL - 1 - t) : t;
    const int rb  = t & 1;

    float pre[4];
#pragma unroll
    for (int g = 0; g < 4; ++g)
        pre[g] = g_xh[((((size_t)(dir * 4 + g) * SL + pos) * NB + n) << 10) + h];

#pragma unroll
    for (int kc = 0; kc < NKC; ++kc) {
        const float* P = &g_part[dir][kc][n][0];
#pragma unroll
        for (int g = 0; g < 4; ++g)
            pre[g] += P[(g << 10) + h];
    }

    const float m  = mask[n * SL + pos];
    float c  = g_cbuf[dir][n][h];
    float hp = g_hbuf[rb][dir][n][h];

    float f  = sigmf(pre[0]);
    float ii = sigmf(pre[1]);
    float o  = sigmf(pre[2]);
    float cn = f * c + ii * tanhf(pre[3]);
    float hn = o * tanhf(cn);
    float hid = (m == 0.0f) ? hp : hn;

    g_cbuf[dir][n][h] = cn;
    g_hbuf[rb ^ 1][dir][n][h] = hid;

    out[(((size_t)n * SL + pos) * 2 + dir) * HH + h] = hid * m;
    if (t == SL - 1) {
        out[(size_t)NB * SL * 2 * HH + ((size_t)n * 2 + dir) * HH + h] = hid;
    }
}

// ---------------------------------------------------------------------------
// Launch
// ---------------------------------------------------------------------------
extern "C" void kernel_launch(void* const* d_in, const int* in_sizes, int n_in,
                              void* d_out, int out_size) {
    const float* x    = (const float*)d_in[0];   // (32,256,1024)
    const float* mask = (const float*)d_in[1];   // (32,256)
    const float* wih  = (const float*)d_in[2];   // (8,1024,1024)
    const float* whh  = (const float*)d_in[3];   // (8,1024,1024)
    const float* bias = (const float*)d_in[4];   // (8,1,1024)
    float* out = (float*)d_out;

    zero_state_kernel<<<192, 256>>>();

    dim3 ggrid(64, 8, 8);
    gemm_ih_kernel<<<ggrid, 256>>>(x, wih, bias);

    dim3 rgrid(16, NKC, 2);
    for (int t = 0; t < SL; t++) {
        recur_gemm_kernel<<<rgrid, 128>>>(whh, t);
        cell_kernel<<<256, 256>>>(mask, out, t);
    }
}

// round 3
// speedup vs baseline: 2.2931x; 1.0159x over previous
#include <cuda_runtime.h>
#include <math.h>

// Problem constants
#define NB   32      // batch
#define SL   256     // sequence length
#define DD   1024    // input dim
#define HH   1024    // hidden dim
#define NKC  8       // k-chunks for split-K recurrence
#define KCH  (HH/NKC) // 128

// ---------------------------------------------------------------------------
// Scratch (device globals)
// ---------------------------------------------------------------------------
__device__ float g_xh[(size_t)8 * SL * NB * HH];          // 268 MB: xh[g][s][n][h]
__device__ float g_hbuf[2][2][NB][HH];                    // [parity][dir][n][h]
__device__ float g_cbuf[2][NB][HH];                       // [dir][n][h]
__device__ float g_part[2][NKC][NB][4 * HH];              // 8.4 MB split-K partials

typedef unsigned long long u64;

__device__ __forceinline__ u64 pk2(float x, float y) {
    u64 r; asm("mov.b64 %0, {%1,%2};" : "=l"(r) : "f"(x), "f"(y)); return r;
}
__device__ __forceinline__ void upk2(u64 v, float& x, float& y) {
    asm("mov.b64 {%0,%1}, %2;" : "=f"(x), "=f"(y) : "l"(v));
}
__device__ __forceinline__ void ffma2(u64& c, u64 a, u64 b) {
    asm("fma.rn.f32x2 %0, %1, %2, %0;" : "+l"(c) : "l"(a), "l"(b));
}
__device__ __forceinline__ float sigmf(float v) {
    return 1.0f / (1.0f + expf(-v));
}

// ---------------------------------------------------------------------------
// Kernel 0: zero init of h and c
// ---------------------------------------------------------------------------
__global__ void zero_state_kernel() {
    int idx = blockIdx.x * blockDim.x + threadIdx.x;
    int total_h = 2 * 2 * NB * HH;
    int total_c = 2 * NB * HH;
    float* h = &g_hbuf[0][0][0][0];
    float* c = &g_cbuf[0][0][0];
    for (int i = idx; i < total_h; i += gridDim.x * blockDim.x) h[i] = 0.0f;
    for (int i = idx; i < total_c; i += gridDim.x * blockDim.x) c[i] = 0.0f;
}

// ---------------------------------------------------------------------------
// Kernel 1: input projection GEMM (f32x2 packed FMA)
//   xh[g][s][n][h] = sum_d x[n][s][d] * wih[g][d][h] + bias[g][h]
// 128x128x8 tile, 256 threads, 8x8 micro-tile (rows paired into f32x2 lanes).
// ---------------------------------------------------------------------------
#define BM 128
#define BN 128
#define BK 8

__global__ __launch_bounds__(256, 2)
void gemm_ih_kernel(const float* __restrict__ x,
                    const float* __restrict__ wih,
                    const float* __restrict__ bias) {
    const int g  = blockIdx.z;
    const int m0 = blockIdx.x * BM;
    const int n0 = blockIdx.y * BN;

    __shared__ float As[BK][BM];
    __shared__ float Bs[BK][BN];

    const float* A = x;                                   // [8192][1024]
    const float* B = wih + (size_t)g * DD * HH;           // [1024][1024]

    const int tid = threadIdx.x;
    const int a_row = tid >> 1;
    const int a_k   = (tid & 1) * 4;
    const int b_k   = tid >> 5;
    const int b_n   = (tid & 31) * 4;

    const int tx = tid & 15;              // col group (8 cols)
    const int ty = tid >> 4;              // row group (8 rows = 4 pairs)

    u64 acc[4][8];
#pragma unroll
    for (int p = 0; p < 4; p++)
#pragma unroll
        for (int j = 0; j < 8; j++) acc[p][j] = pk2(0.0f, 0.0f);

    for (int k0 = 0; k0 < DD; k0 += BK) {
        float4 av = *(const float4*)(A + (size_t)(m0 + a_row) * DD + k0 + a_k);
        As[a_k + 0][a_row] = av.x;
        As[a_k + 1][a_row] = av.y;
        As[a_k + 2][a_row] = av.z;
        As[a_k + 3][a_row] = av.w;
        *(float4*)(&Bs[b_k][b_n]) =
            *(const float4*)(B + (size_t)(k0 + b_k) * HH + n0 + b_n);
        __syncthreads();

#pragma unroll
        for (int k = 0; k < BK; k++) {
            u64 ap[4];
#pragma unroll
            for (int p = 0; p < 4; p++)
                ap[p] = *(const u64*)&As[k][ty * 8 + 2 * p];
            float4 b0 = *(const float4*)&Bs[k][tx * 8];
            float4 b1 = *(const float4*)&Bs[k][tx * 8 + 4];
            u64 bb[8];
            bb[0] = pk2(b0.x, b0.x); bb[1] = pk2(b0.y, b0.y);
            bb[2] = pk2(b0.z, b0.z); bb[3] = pk2(b0.w, b0.w);
            bb[4] = pk2(b1.x, b1.x); bb[5] = pk2(b1.y, b1.y);
            bb[6] = pk2(b1.z, b1.z); bb[7] = pk2(b1.w, b1.w);
#pragma unroll
            for (int p = 0; p < 4; p++)
#pragma unroll
                for (int j = 0; j < 8; j++)
                    ffma2(acc[p][j], ap[p], bb[j]);
        }
        __syncthreads();
    }

    // Epilogue: scatter into xh[g][s][n][h] with bias
    const int col0 = n0 + tx * 8;
#pragma unroll
    for (int p = 0; p < 4; p++) {
        float lo[8], hi[8];
#pragma unroll
        for (int j = 0; j < 8; j++) upk2(acc[p][j], lo[j], hi[j]);
#pragma unroll
        for (int half = 0; half < 2; half++) {
            int row  = m0 + ty * 8 + 2 * p + half;    // r = n*256 + s
            int nidx = row >> 8;
            int s    = row & 255;
            size_t base = ((((size_t)g * SL + s) * NB + nidx) << 10) + col0;
            const float* v = half ? hi : lo;
#pragma unroll
            for (int j = 0; j < 8; j++)
                g_xh[base + j] = v[j] + bias[g * HH + col0 + j];
        }
    }
}

// ---------------------------------------------------------------------------
// Kernel 2: recurrence GEMM, split-K.
//   partial[dir][kc][n][col] = sum_{k in chunk kc} h_prev[n][k] * Whh[dir*4+g][k][h]
//   where col = g*1024 + h.  Tile: 32n x 256col, K-chunk 128.
// grid (16 htiles, 8 kchunks, 2 dirs) = 256 blocks, 128 threads.
// Micro-tile 8n x 8col as 4 row-pairs x 8 cols of f32x2.
// ---------------------------------------------------------------------------
__global__ __launch_bounds__(128)
void recur_gemm_kernel(const float* __restrict__ whh, int t) {
    const int ht  = blockIdx.x;            // 0..15
    const int kc  = blockIdx.y;            // 0..NKC-1
    const int dir = blockIdx.z;            // 0..1
    const int tid = threadIdx.x;           // 0..127
    const int col0 = ht * 256;
    const int gate = col0 >> 10;           // tile lies in a single gate
    const int hcol = col0 & 1023;
    const int rb   = t & 1;

    __shared__ float As[16][34];           // [k][n], padded to 8B-aligned rows
    __shared__ float Bs[16][256];          // [k][col]

    const float* hprev = &g_hbuf[rb][dir][0][0];             // [32][1024]
    const float* W = whh + (((size_t)(dir * 4 + gate)) << 20) + hcol;

    const int tr = tid >> 5;               // 0..3 -> rows tr*8..tr*8+7
    const int tc = tid & 31;               // 0..31 -> cols tc*8..tc*8+7

    const int an = tid & 31;               // h-tile load: batch row
    const int aq = (tid >> 5) * 4;         // h-tile load: k quad

    u64 acc[4][8];
#pragma unroll
    for (int p = 0; p < 4; p++)
#pragma unroll
        for (int j = 0; j < 8; j++) acc[p][j] = pk2(0.0f, 0.0f);

    for (int it = 0; it < KCH / 16; ++it) {      // 8 iterations of BK=16
        const int kb = kc * KCH + it * 16;

        // Stage global loads in registers (overlaps with previous compute)
        float4 hv = *(const float4*)(hprev + ((size_t)an << 10) + kb + aq);
        float4 wv[8];
#pragma unroll
        for (int r = 0; r < 8; ++r) {
            int lin = tid + r * 128;             // 0..1023 float4 slots
            int kk  = lin >> 6;
            int c4  = (lin & 63) * 4;
            wv[r] = *(const float4*)(W + (size_t)(kb + kk) * HH + c4);
        }
        __syncthreads();                          // prev-iter readers done

        As[aq + 0][an] = hv.x; As[aq + 1][an] = hv.y;
        As[aq + 2][an] = hv.z; As[aq + 3][an] = hv.w;
#pragma unroll
        for (int r = 0; r < 8; ++r) {
            int lin = tid + r * 128;
            *(float4*)&Bs[lin >> 6][(lin & 63) * 4] = wv[r];
        }
        __syncthreads();

#pragma unroll
        for (int kk = 0; kk < 16; ++kk) {
            u64 ap[4];
#pragma unroll
            for (int p = 0; p < 4; p++)
                ap[p] = *(const u64*)&As[kk][tr * 8 + 2 * p];   // broadcast in warp
            float4 b0 = *(const float4*)&Bs[kk][tc * 8];
            float4 b1 = *(const float4*)&Bs[kk][tc * 8 + 4];
            u64 bb[8];
            bb[0] = pk2(b0.x, b0.x); bb[1] = pk2(b0.y, b0.y);
            bb[2] = pk2(b0.z, b0.z); bb[3] = pk2(b0.w, b0.w);
            bb[4] = pk2(b1.x, b1.x); bb[5] = pk2(b1.y, b1.y);
            bb[6] = pk2(b1.z, b1.z); bb[7] = pk2(b1.w, b1.w);
#pragma unroll
            for (int p = 0; p < 4; p++)
#pragma unroll
                for (int j = 0; j < 8; j++)
                    ffma2(acc[p][j], ap[p], bb[j]);
        }
    }

    // Write partials: rows are batch n, cols are col0 + tc*8 + j
    float* P = &g_part[dir][kc][0][0];            // [32][4096]
#pragma unroll
    for (int p = 0; p < 4; p++) {
        float lo[8], hi[8];
#pragma unroll
        for (int j = 0; j < 8; j++) upk2(acc[p][j], lo[j], hi[j]);
        int r0 = tr * 8 + 2 * p;
        size_t base0 = (size_t)r0 * 4096 + col0 + tc * 8;
        size_t base1 = base0 + 4096;
        *(float4*)&P[base0]     = make_float4(lo[0], lo[1], lo[2], lo[3]);
        *(float4*)&P[base0 + 4] = make_float4(lo[4], lo[5], lo[6], lo[7]);
        *(float4*)&P[base1]     = make_float4(hi[0], hi[1], hi[2], hi[3]);
        *(float4*)&P[base1 + 4] = make_float4(hi[4], hi[5], hi[6], hi[7]);
    }
}

// ---------------------------------------------------------------------------
// Kernel 3: reduce partials + LSTM pointwise cell (float4 lanes).
// 16384 threads: one per (dir, n, h-quad).
// ---------------------------------------------------------------------------
__global__ __launch_bounds__(256)
void cell_kernel(const float* __restrict__ mask, float* __restrict__ out, int t) {
    const int idx = blockIdx.x * 256 + threadIdx.x;   // 0..16383
    const int h4  = idx & 255;                        // h quad index
    const int h   = h4 * 4;
    const int n   = (idx >> 8) & 31;
    const int dir = idx >> 13;
    const int pos = dir ? (SL - 1 - t) : t;
    const int rb  = t & 1;

    float4 pre[4];
#pragma unroll
    for (int g = 0; g < 4; ++g)
        pre[g] = *(const float4*)&g_xh[
            ((((size_t)(dir * 4 + g) * SL + pos) * NB + n) << 10) + h];

#pragma unroll
    for (int kc = 0; kc < NKC; ++kc) {
        const float* P = &g_part[dir][kc][n][0];
#pragma unroll
        for (int g = 0; g < 4; ++g) {
            float4 v = *(const float4*)&P[(g << 10) + h];
            pre[g].x += v.x; pre[g].y += v.y;
            pre[g].z += v.z; pre[g].w += v.w;
        }
    }

    const float m  = mask[n * SL + pos];
    float4 c_old = *(const float4*)&g_cbuf[dir][n][h];
    float4 h_old = *(const float4*)&g_hbuf[rb][dir][n][h];

    float co[4] = {c_old.x, c_old.y, c_old.z, c_old.w};
    float ho[4] = {h_old.x, h_old.y, h_old.z, h_old.w};
    float fp[4] = {pre[0].x, pre[0].y, pre[0].z, pre[0].w};
    float ip[4] = {pre[1].x, pre[1].y, pre[1].z, pre[1].w};
    float op[4] = {pre[2].x, pre[2].y, pre[2].z, pre[2].w};
    float gp[4] = {pre[3].x, pre[3].y, pre[3].z, pre[3].w};

    float cn[4], hid[4], om[4];
#pragma unroll
    for (int j = 0; j < 4; ++j) {
        float f  = sigmf(fp[j]);
        float ii = sigmf(ip[j]);
        float o  = sigmf(op[j]);
        cn[j]  = f * co[j] + ii * tanhf(gp[j]);
        float hn = o * tanhf(cn[j]);
        hid[j] = (m == 0.0f) ? ho[j] : hn;
        om[j]  = hid[j] * m;
    }

    *(float4*)&g_cbuf[dir][n][h] = make_float4(cn[0], cn[1], cn[2], cn[3]);
    *(float4*)&g_hbuf[rb ^ 1][dir][n][h] =
        make_float4(hid[0], hid[1], hid[2], hid[3]);

    *(float4*)&out[(((size_t)n * SL + pos) * 2 + dir) * HH + h] =
        make_float4(om[0], om[1], om[2], om[3]);
    if (t == SL - 1) {
        *(float4*)&out[(size_t)NB * SL * 2 * HH + ((size_t)n * 2 + dir) * HH + h] =
            make_float4(hid[0], hid[1], hid[2], hid[3]);
    }
}

// ---------------------------------------------------------------------------
// Launch
// ---------------------------------------------------------------------------
extern "C" void kernel_launch(void* const* d_in, const int* in_sizes, int n_in,
                              void* d_out, int out_size) {
    const float* x    = (const float*)d_in[0];   // (32,256,1024)
    const float* mask = (const float*)d_in[1];   // (32,256)
    const float* wih  = (const float*)d_in[2];   // (8,1024,1024)
    const float* whh  = (const float*)d_in[3];   // (8,1024,1024)
    const float* bias = (const float*)d_in[4];   // (8,1,1024)
    float* out = (float*)d_out;

    zero_state_kernel<<<192, 256>>>();

    dim3 ggrid(64, 8, 8);
    gemm_ih_kernel<<<ggrid, 256>>>(x, wih, bias);

    dim3 rgrid(16, NKC, 2);
    for (int t = 0; t < SL; t++) {
        recur_gemm_kernel<<<rgrid, 128>>>(whh, t);
        cell_kernel<<<64, 256>>>(mask, out, t);
    }
}

// round 4
// speedup vs baseline: 2.4467x; 1.0670x over previous
#include <cuda_runtime.h>
#include <math.h>

// Problem constants
#define NB   32      // batch
#define SL   256     // sequence length
#define DD   1024    // input dim
#define HH   1024    // hidden dim
#define NKC  8       // k-chunks for split-K recurrence
#define KCH  128     // K per chunk
#define NBLK 256     // persistent blocks (16 ht * 8 kc * 2 dir)

// ---------------------------------------------------------------------------
// Scratch (device globals)
// ---------------------------------------------------------------------------
__device__ float g_xh[(size_t)8 * SL * NB * HH];   // 268 MB: xh[g][s][n][h]
__device__ float g_h[2][NB][HH];                   // hidden state [dir][n][k]
__device__ float g_part[2][NKC][NB][4 * HH];       // split-K partials
__device__ int   g_bar[2][SL];                     // grid barrier counters

typedef unsigned long long u64;

__device__ __forceinline__ u64 pk2(float x, float y) {
    u64 r; asm("mov.b64 %0, {%1,%2};" : "=l"(r) : "f"(x), "f"(y)); return r;
}
__device__ __forceinline__ void upk2(u64 v, float& x, float& y) {
    asm("mov.b64 {%0,%1}, %2;" : "=f"(x), "=f"(y) : "l"(v));
}
__device__ __forceinline__ void ffma2(u64& c, u64 a, u64 b) {
    asm("fma.rn.f32x2 %0, %1, %2, %0;" : "+l"(c) : "l"(a), "l"(b));
}
__device__ __forceinline__ float sigmf(float v) {
    return 1.0f / (1.0f + expf(-v));
}

// ---------------------------------------------------------------------------
// Kernel 0: zero init of h and barrier counters
// ---------------------------------------------------------------------------
__global__ void zero_state_kernel() {
    int idx = blockIdx.x * blockDim.x + threadIdx.x;
    int total_h = 2 * NB * HH;
    float* h = &g_h[0][0][0];
    for (int i = idx; i < total_h; i += gridDim.x * blockDim.x) h[i] = 0.0f;
    int* bar = &g_bar[0][0];
    for (int i = idx; i < 2 * SL; i += gridDim.x * blockDim.x) bar[i] = 0;
}

// ---------------------------------------------------------------------------
// Kernel 1: input projection GEMM (f32x2, column-paired lanes, no dup movs)
//   xh[g][s][n][h] = sum_d x[n][s][d] * wih[g][d][h] + bias[g][h]
// 128x128x8 tile, 256 threads. Micro-tile: 8 rows x 4 col-pairs.
// A values duplicated once into smem as u64 {a,a}; B read as natural pairs.
// ---------------------------------------------------------------------------
__global__ __launch_bounds__(256, 2)
void gemm_ih_kernel(const float* __restrict__ x,
                    const float* __restrict__ wih,
                    const float* __restrict__ bias) {
    const int g  = blockIdx.z;
    const int m0 = blockIdx.x * 128;
    const int n0 = blockIdx.y * 128;

    __shared__ u64   As2[8][129];     // [k][row] duplicated {a,a}
    __shared__ float Bs[8][128];      // [k][col]

    const float* A = x;                                   // [8192][1024]
    const float* B = wih + (size_t)g * DD * HH;           // [1024][1024]

    const int tid   = threadIdx.x;
    const int a_row = tid >> 1;            // 0..127
    const int a_k   = (tid & 1) * 4;       // 0 or 4
    const int b_k   = tid >> 5;            // 0..7
    const int b_n   = (tid & 31) * 4;      // 0..124

    const int tx = tid & 15;               // col-pair lane: cols 2*tx + 32*j
    const int ty = tid >> 4;               // row group: rows ty*8..+7

    u64 acc[8][4];
#pragma unroll
    for (int i = 0; i < 8; i++)
#pragma unroll
        for (int j = 0; j < 4; j++) acc[i][j] = pk2(0.0f, 0.0f);

    for (int k0 = 0; k0 < DD; k0 += 8) {
        float4 av = *(const float4*)(A + (size_t)(m0 + a_row) * DD + k0 + a_k);
        float4 bv = *(const float4*)(B + (size_t)(k0 + b_k) * HH + n0 + b_n);
        __syncthreads();
        As2[a_k + 0][a_row] = pk2(av.x, av.x);
        As2[a_k + 1][a_row] = pk2(av.y, av.y);
        As2[a_k + 2][a_row] = pk2(av.z, av.z);
        As2[a_k + 3][a_row] = pk2(av.w, av.w);
        *(float4*)&Bs[b_k][b_n] = bv;
        __syncthreads();

#pragma unroll
        for (int k = 0; k < 8; k++) {
            u64 a8[8], b4[4];
#pragma unroll
            for (int i = 0; i < 8; i++) a8[i] = As2[k][ty * 8 + i];
#pragma unroll
            for (int j = 0; j < 4; j++) b4[j] = *(const u64*)&Bs[k][32 * j + 2 * tx];
#pragma unroll
            for (int i = 0; i < 8; i++)
#pragma unroll
                for (int j = 0; j < 4; j++)
                    ffma2(acc[i][j], a8[i], b4[j]);
        }
    }

    // Epilogue: scatter into xh[g][s][n][h] with bias. cols = n0 + 32j + 2tx.
    float2 bz[4];
#pragma unroll
    for (int j = 0; j < 4; j++)
        bz[j] = *(const float2*)&bias[g * HH + n0 + 32 * j + 2 * tx];

#pragma unroll
    for (int i = 0; i < 8; i++) {
        int row  = m0 + ty * 8 + i;        // r = n*256 + s
        int nidx = row >> 8;
        int s    = row & 255;
        size_t base = (((size_t)g * SL + s) * NB + nidx) << 10;
#pragma unroll
        for (int j = 0; j < 4; j++) {
            float lo, hi; upk2(acc[i][j], lo, hi);
            *(float2*)&g_xh[base + n0 + 32 * j + 2 * tx] =
                make_float2(lo + bz[j].x, hi + bz[j].y);
        }
    }
}

// ---------------------------------------------------------------------------
// Kernel 2: persistent fused recurrence. ONE launch for all 256 steps.
// 256 blocks x 128 threads. Block id -> (dir, kc, ht).
//  GEMM phase:  partial[dir][kc][n][col] over K-chunk kc, cols ht*256..+255
//  barrier
//  cell phase:  block handles n in [kc*4, kc*4+4), h in [ht*64, ht*64+64)
//               c and h_old live in registers across all steps.
//  barrier
// ---------------------------------------------------------------------------
__global__ __launch_bounds__(128)
void bilstm_persistent(const float* __restrict__ whh,
                       const float* __restrict__ mask,
                       float* __restrict__ out) {
    const int bid = blockIdx.x;
    const int dir = bid & 1;
    const int kc  = (bid >> 1) & 7;
    const int ht  = bid >> 4;              // 0..15
    const int tid = threadIdx.x;

    // GEMM constants
    const int col0 = ht * 256;
    const int gate = col0 >> 10;           // tile within a single gate
    const int hcol = col0 & 1023;
    const float* W = whh + (((size_t)(dir * 4 + gate)) << 20) + hcol;
    const int tr = tid >> 5;               // rows tr*8..+7 (n)
    const int tc = tid & 31;               // col-pairs: cols 64*j + 2*tc
    const int an = tid & 31;               // A loader: batch row
    const int aq = (tid >> 5) * 4;         // A loader: k quad

    // Cell constants
    const int cn = kc * 4 + (tid >> 5);    // batch row for cell
    const int ch = ht * 64 + (tid & 31) * 2;  // h pair for cell
    float cc0 = 0.0f, cc1 = 0.0f;          // cell state (registers!)
    float hr0 = 0.0f, hr1 = 0.0f;          // hidden state (registers)
    const float* mrow = mask + cn * SL;

    __shared__ u64   As2[16][33];          // [k][n] duplicated {h,h}
    __shared__ float Bs[16][256];          // [k][col]

    for (int t = 0; t < SL; t++) {
        // ================= GEMM phase =================
        u64 acc[8][4];
#pragma unroll
        for (int i = 0; i < 8; i++)
#pragma unroll
            for (int j = 0; j < 4; j++) acc[i][j] = pk2(0.0f, 0.0f);

        for (int it = 0; it < KCH / 16; ++it) {
            const int kb = kc * KCH + it * 16;

            // Register staging (bypass L1 for h: written by other SMs)
            float4 hv = __ldcg((const float4*)&g_h[dir][an][kb + aq]);
            float4 wv[8];
#pragma unroll
            for (int r = 0; r < 8; ++r) {
                int lin = tid + r * 128;
                int kk  = lin >> 6;
                int c4  = (lin & 63) * 4;
                wv[r] = *(const float4*)(W + (size_t)(kb + kk) * HH + c4);
            }
            __syncthreads();               // prev-iter readers done
            As2[aq + 0][an] = pk2(hv.x, hv.x);
            As2[aq + 1][an] = pk2(hv.y, hv.y);
            As2[aq + 2][an] = pk2(hv.z, hv.z);
            As2[aq + 3][an] = pk2(hv.w, hv.w);
#pragma unroll
            for (int r = 0; r < 8; ++r) {
                int lin = tid + r * 128;
                *(float4*)&Bs[lin >> 6][(lin & 63) * 4] = wv[r];
            }
            __syncthreads();

#pragma unroll
            for (int kk = 0; kk < 16; ++kk) {
                u64 a8[8], b4[4];
#pragma unroll
                for (int i = 0; i < 8; i++) a8[i] = As2[kk][tr * 8 + i];
#pragma unroll
                for (int j = 0; j < 4; j++)
                    b4[j] = *(const u64*)&Bs[kk][64 * j + 2 * tc];
#pragma unroll
                for (int i = 0; i < 8; i++)
#pragma unroll
                    for (int j = 0; j < 4; j++)
                        ffma2(acc[i][j], a8[i], b4[j]);
            }
        }

        // Write partials: P[n][col0 + 64j + 2tc]
        {
            float* P = &g_part[dir][kc][0][0];
#pragma unroll
            for (int i = 0; i < 8; i++) {
                int row = tr * 8 + i;
                size_t rb = (size_t)row * 4096 + col0 + 2 * tc;
#pragma unroll
                for (int j = 0; j < 4; j++) {
                    float lo, hi; upk2(acc[i][j], lo, hi);
                    *(float2*)&P[rb + 64 * j] = make_float2(lo, hi);
                }
            }
        }

        // ================= barrier: partials ready =================
        __threadfence();
        __syncthreads();
        if (tid == 0) {
            atomicAdd(&g_bar[0][t], 1);
            while (*(volatile int*)&g_bar[0][t] < NBLK) __nanosleep(64);
        }
        __syncthreads();

        // ================= cell phase =================
        {
            const int pos = dir ? (SL - 1 - t) : t;
            float2 pre[4];
#pragma unroll
            for (int g = 0; g < 4; ++g)
                pre[g] = *(const float2*)&g_xh[
                    ((((size_t)(dir * 4 + g) * SL + pos) * NB + cn) << 10) + ch];
#pragma unroll
            for (int kcp = 0; kcp < NKC; ++kcp) {
#pragma unroll
                for (int g = 0; g < 4; ++g) {
                    float2 v = __ldcg((const float2*)
                        &g_part[dir][kcp][cn][(g << 10) + ch]);
                    pre[g].x += v.x; pre[g].y += v.y;
                }
            }
            const float m = mrow[pos];

            float f0 = sigmf(pre[0].x), f1 = sigmf(pre[0].y);
            float i0 = sigmf(pre[1].x), i1 = sigmf(pre[1].y);
            float o0 = sigmf(pre[2].x), o1 = sigmf(pre[2].y);
            cc0 = f0 * cc0 + i0 * tanhf(pre[3].x);
            cc1 = f1 * cc1 + i1 * tanhf(pre[3].y);
            float hn0 = o0 * tanhf(cc0);
            float hn1 = o1 * tanhf(cc1);
            hr0 = (m == 0.0f) ? hr0 : hn0;
            hr1 = (m == 0.0f) ? hr1 : hn1;

            *(float2*)&g_h[dir][cn][ch] = make_float2(hr0, hr1);
            *(float2*)&out[(((size_t)cn * SL + pos) * 2 + dir) * HH + ch] =
                make_float2(hr0 * m, hr1 * m);
            if (t == SL - 1) {
                *(float2*)&out[(size_t)NB * SL * 2 * HH +
                               ((size_t)cn * 2 + dir) * HH + ch] =
                    make_float2(hr0, hr1);
            }
        }

        // ================= barrier: h ready =================
        __threadfence();
        __syncthreads();
        if (tid == 0) {
            atomicAdd(&g_bar[1][t], 1);
            while (*(volatile int*)&g_bar[1][t] < NBLK) __nanosleep(64);
        }
        __syncthreads();
    }
}

// ---------------------------------------------------------------------------
// Launch
// ---------------------------------------------------------------------------
extern "C" void kernel_launch(void* const* d_in, const int* in_sizes, int n_in,
                              void* d_out, int out_size) {
    const float* x    = (const float*)d_in[0];   // (32,256,1024)
    const float* mask = (const float*)d_in[1];   // (32,256)
    const float* wih  = (const float*)d_in[2];   // (8,1024,1024)
    const float* whh  = (const float*)d_in[3];   // (8,1024,1024)
    const float* bias = (const float*)d_in[4];   // (8,1,1024)
    float* out = (float*)d_out;

    zero_state_kernel<<<64, 256>>>();

    dim3 ggrid(64, 8, 8);
    gemm_ih_kernel<<<ggrid, 256>>>(x, wih, bias);

    bilstm_persistent<<<NBLK, 128>>>(whh, mask, out);
}

// round 6
// speedup vs baseline: 3.0782x; 1.2581x over previous
#include <cuda_runtime.h>
#include <cuda_bf16.h>
#include <math.h>
#include <cstdint>

// Problem constants
#define NB   32      // batch
#define SL   256     // sequence length
#define DD   1024    // input dim
#define HH   1024    // hidden dim
#define NKC  8       // k-chunks for split-K recurrence
#define KCH  128     // K per chunk
#define NBLK 256     // persistent blocks (16 ht * 8 kc * 2 dir)

// ---------------------------------------------------------------------------
// Scratch (device globals)
// ---------------------------------------------------------------------------
__device__ float g_xh[(size_t)8 * SL * NB * HH];   // 268 MB: xh[g][s][n][h]
__device__ float g_h[2][NB][HH];                   // hidden state [dir][n][k]
__device__ float g_part[2][NKC][NB][4 * HH];       // split-K partials
__device__ int   g_bar[2][SL];                     // grid barrier counters
// bf16 split operands for the input GEMM
__device__ __nv_bfloat16 g_xa_hi[(size_t)NB * SL * DD];
__device__ __nv_bfloat16 g_xa_lo[(size_t)NB * SL * DD];
__device__ __nv_bfloat16 g_wt_hi[(size_t)8 * HH * DD];   // [g][n][k] (transposed)
__device__ __nv_bfloat16 g_wt_lo[(size_t)8 * HH * DD];

typedef unsigned long long u64;

__device__ __forceinline__ u64 pk2(float x, float y) {
    u64 r; asm("mov.b64 %0, {%1,%2};" : "=l"(r) : "f"(x), "f"(y)); return r;
}
__device__ __forceinline__ void upk2(u64 v, float& x, float& y) {
    asm("mov.b64 {%0,%1}, %2;" : "=f"(x), "=f"(y) : "l"(v));
}
__device__ __forceinline__ void ffma2(u64& c, u64 a, u64 b) {
    asm("fma.rn.f32x2 %0, %1, %2, %0;" : "+l"(c) : "l"(a), "l"(b));
}
__device__ __forceinline__ float sigmf(float v) {
    return 1.0f / (1.0f + expf(-v));
}

// mma.sync m16n8k16 bf16, fp32 accumulate (legacy tensor-core path, sm_80+)
__device__ __forceinline__ void mma16816(float* c, const uint32_t* a,
                                         const uint32_t* b) {
    asm volatile(
        "mma.sync.aligned.m16n8k16.row.col.f32.bf16.bf16.f32 "
        "{%0,%1,%2,%3}, {%4,%5,%6,%7}, {%8,%9}, {%0,%1,%2,%3};"
        : "+f"(c[0]), "+f"(c[1]), "+f"(c[2]), "+f"(c[3])
        : "r"(a[0]), "r"(a[1]), "r"(a[2]), "r"(a[3]), "r"(b[0]), "r"(b[1]));
}

// ---------------------------------------------------------------------------
// Kernel 0: zero init of h and barrier counters
// ---------------------------------------------------------------------------
__global__ void zero_state_kernel() {
    int idx = blockIdx.x * blockDim.x + threadIdx.x;
    int total_h = 2 * NB * HH;
    float* h = &g_h[0][0][0];
    for (int i = idx; i < total_h; i += gridDim.x * blockDim.x) h[i] = 0.0f;
    int* bar = &g_bar[0][0];
    for (int i = idx; i < 2 * SL; i += gridDim.x * blockDim.x) bar[i] = 0;
}

// ---------------------------------------------------------------------------
// Kernel A: convert x -> bf16 hi/lo   (rows r = n*SL+s, cols d)
// ---------------------------------------------------------------------------
__global__ __launch_bounds__(256)
void convert_x_kernel(const float* __restrict__ x) {
    const size_t total4 = (size_t)NB * SL * DD / 4;
    for (size_t i = blockIdx.x * 256 + threadIdx.x; i < total4;
         i += (size_t)gridDim.x * 256) {
        float4 v = *(const float4*)(x + i * 4);
        __nv_bfloat16 h0 = __float2bfloat16_rn(v.x);
        __nv_bfloat16 h1 = __float2bfloat16_rn(v.y);
        __nv_bfloat16 h2 = __float2bfloat16_rn(v.z);
        __nv_bfloat16 h3 = __float2bfloat16_rn(v.w);
        __nv_bfloat16 l0 = __float2bfloat16_rn(v.x - __bfloat162float(h0));
        __nv_bfloat16 l1 = __float2bfloat16_rn(v.y - __bfloat162float(h1));
        __nv_bfloat16 l2 = __float2bfloat16_rn(v.z - __bfloat162float(h2));
        __nv_bfloat16 l3 = __float2bfloat16_rn(v.w - __bfloat162float(h3));
        __nv_bfloat162 hh0 = __halves2bfloat162(h0, h1);
        __nv_bfloat162 hh1 = __halves2bfloat162(h2, h3);
        __nv_bfloat162 ll0 = __halves2bfloat162(l0, l1);
        __nv_bfloat162 ll1 = __halves2bfloat162(l2, l3);
        *(uint2*)(g_xa_hi + i * 4) = make_uint2(
            *(uint32_t*)&hh0, *(uint32_t*)&hh1);
        *(uint2*)(g_xa_lo + i * 4) = make_uint2(
            *(uint32_t*)&ll0, *(uint32_t*)&ll1);
    }
}

// ---------------------------------------------------------------------------
// Kernel B: transpose + convert W_ih -> wt[g][n][k] bf16 hi/lo
// ---------------------------------------------------------------------------
__global__ void convert_w_kernel(const float* __restrict__ w) {
    __shared__ float tile[32][33];
    const int g  = blockIdx.z;
    const int k0 = blockIdx.x * 32;
    const int n0 = blockIdx.y * 32;
    const int tx = threadIdx.x, ty = threadIdx.y;   // (32, 8)
    const float* W = w + ((size_t)g << 20);
#pragma unroll
    for (int i = 0; i < 4; i++)
        tile[ty + 8 * i][tx] = W[(size_t)(k0 + ty + 8 * i) * HH + n0 + tx];
    __syncthreads();
#pragma unroll
    for (int i = 0; i < 4; i++) {
        float v = tile[tx][ty + 8 * i];     // = W[k0+tx][n0+ty+8i]
        __nv_bfloat16 hi = __float2bfloat16_rn(v);
        __nv_bfloat16 lo = __float2bfloat16_rn(v - __bfloat162float(hi));
        size_t idx = ((size_t)g << 20) + (size_t)(n0 + ty + 8 * i) * DD + k0 + tx;
        g_wt_hi[idx] = hi;
        g_wt_lo[idx] = lo;
    }
}

// ---------------------------------------------------------------------------
// Kernel C: mma.sync bf16x3 input-projection GEMM.
//   D[m][n] = sum_k x[m][k]*W[k][n] via xh*wh + xh*wl + xl*wh, fp32 accum.
// CTA tile 128(m) x 64(n), 8 warps (warp tile 32x32), K-chunk 32.
// A: [m][k] row-major (bf16 hi/lo), B: [n][k] (col-major for mma) hi/lo.
// grid (64, 16, 8), 256 threads.
// ---------------------------------------------------------------------------
#define ASTR 40   // smem k-stride (bf16) for A/B tiles: conflict-free frag loads

__global__ __launch_bounds__(256, 2)
void gemm_ih_mma_kernel(const float* __restrict__ bias) {
    __shared__ __nv_bfloat16 As_hi[128][ASTR];
    __shared__ __nv_bfloat16 As_lo[128][ASTR];
    __shared__ __nv_bfloat16 Bs_hi[64][ASTR];
    __shared__ __nv_bfloat16 Bs_lo[64][ASTR];

    const int g   = blockIdx.z;
    const int m0  = blockIdx.x * 128;
    const int n0  = blockIdx.y * 64;
    const int tid = threadIdx.x;
    const int wid = tid >> 5;
    const int lid = tid & 31;
    const int wm  = wid & 3;          // warp m-tile: rows wm*32..+31
    const int wn  = wid >> 2;         // warp n-tile: cols wn*32..+31

    const __nv_bfloat16* a_hi = g_xa_hi;
    const __nv_bfloat16* a_lo = g_xa_lo;
    const __nv_bfloat16* b_hi = g_wt_hi + ((size_t)g << 20);
    const __nv_bfloat16* b_lo = g_wt_lo + ((size_t)g << 20);

    float acc[2][4][4];               // [mt][nt][reg]
#pragma unroll
    for (int mt = 0; mt < 2; mt++)
#pragma unroll
        for (int nt = 0; nt < 4; nt++)
#pragma unroll
            for (int r = 0; r < 4; r++) acc[mt][nt][r] = 0.0f;

    // Fragment smem coordinates (per thread)
    const int fq = lid >> 2;          // quad row: m/n offset
    const int fk = (lid & 3) * 2;     // k element offset

    for (int k0 = 0; k0 < DD; k0 += 32) {
        __syncthreads();
        // Load A tiles: 512 uint4 slots (hi), each thread 2
#pragma unroll
        for (int s = 0; s < 2; s++) {
            int lin = tid + s * 256;          // 0..511
            int row = lin >> 2;
            int kq  = (lin & 3) * 8;
            *(uint4*)&As_hi[row][kq] =
                *(const uint4*)(a_hi + (size_t)(m0 + row) * DD + k0 + kq);
            *(uint4*)&As_lo[row][kq] =
                *(const uint4*)(a_lo + (size_t)(m0 + row) * DD + k0 + kq);
        }
        // Load B tiles: 256 uint4 slots, each thread 1
        {
            int row = tid >> 2;
            int kq  = (tid & 3) * 8;
            *(uint4*)&Bs_hi[row][kq] =
                *(const uint4*)(b_hi + (size_t)(n0 + row) * DD + k0 + kq);
            *(uint4*)&Bs_lo[row][kq] =
                *(const uint4*)(b_lo + (size_t)(n0 + row) * DD + k0 + kq);
        }
        __syncthreads();

#pragma unroll
        for (int ks = 0; ks < 32; ks += 16) {
            uint32_t Ah[2][4], Al[2][4], Bh[4][2], Bl[4][2];
#pragma unroll
            for (int mt = 0; mt < 2; mt++) {
                int mb = wm * 32 + mt * 16;
                Ah[mt][0] = *(const uint32_t*)&As_hi[mb + fq][ks + fk];
                Ah[mt][1] = *(const uint32_t*)&As_hi[mb + fq + 8][ks + fk];
                Ah[mt][2] = *(const uint32_t*)&As_hi[mb + fq][ks + fk + 8];
                Ah[mt][3] = *(const uint32_t*)&As_hi[mb + fq + 8][ks + fk + 8];
                Al[mt][0] = *(const uint32_t*)&As_lo[mb + fq][ks + fk];
                Al[mt][1] = *(const uint32_t*)&As_lo[mb + fq + 8][ks + fk];
                Al[mt][2] = *(const uint32_t*)&As_lo[mb + fq][ks + fk + 8];
                Al[mt][3] = *(const uint32_t*)&As_lo[mb + fq + 8][ks + fk + 8];
            }
#pragma unroll
            for (int nt = 0; nt < 4; nt++) {
                int nb = wn * 32 + nt * 8;
                Bh[nt][0] = *(const uint32_t*)&Bs_hi[nb + fq][ks + fk];
                Bh[nt][1] = *(const uint32_t*)&Bs_hi[nb + fq][ks + fk + 8];
                Bl[nt][0] = *(const uint32_t*)&Bs_lo[nb + fq][ks + fk];
                Bl[nt][1] = *(const uint32_t*)&Bs_lo[nb + fq][ks + fk + 8];
            }
#pragma unroll
            for (int mt = 0; mt < 2; mt++)
#pragma unroll
                for (int nt = 0; nt < 4; nt++) {
                    mma16816(acc[mt][nt], Ah[mt], Bh[nt]);
                    mma16816(acc[mt][nt], Ah[mt], Bl[nt]);
                    mma16816(acc[mt][nt], Al[mt], Bh[nt]);
                }
        }
    }

    // Epilogue: acc[mt][nt] regs {c0,c1}=(row=fq, col=fk2..+1), {c2,c3}=(row+8)
#pragma unroll
    for (int mt = 0; mt < 2; mt++) {
#pragma unroll
        for (int nt = 0; nt < 4; nt++) {
            int col = n0 + wn * 32 + nt * 8 + (lid & 3) * 2;
            float2 bz = *(const float2*)&bias[g * HH + col];
#pragma unroll
            for (int half = 0; half < 2; half++) {
                int row  = m0 + wm * 32 + mt * 16 + fq + half * 8;
                int nidx = row >> 8;
                int s    = row & 255;
                size_t base = ((((size_t)g * SL + s) * NB + nidx) << 10) + col;
                *(float2*)&g_xh[base] = make_float2(
                    acc[mt][nt][half * 2 + 0] + bz.x,
                    acc[mt][nt][half * 2 + 1] + bz.y);
            }
        }
    }
}

// ---------------------------------------------------------------------------
// Kernel 2: persistent fused recurrence (pipelined staging + xh prefetch).
// 256 blocks x 128 threads. Block id -> (dir, kc, ht).
// ---------------------------------------------------------------------------
__global__ __launch_bounds__(128)
void bilstm_persistent(const float* __restrict__ whh,
                       const float* __restrict__ mask,
                       float* __restrict__ out) {
    const int bid = blockIdx.x;
    const int dir = bid & 1;
    const int kc  = (bid >> 1) & 7;
    const int ht  = bid >> 4;              // 0..15
    const int tid = threadIdx.x;

    // GEMM constants
    const int col0 = ht * 256;
    const int gate = col0 >> 10;           // tile within a single gate
    const int hcol = col0 & 1023;
    const float* W = whh + (((size_t)(dir * 4 + gate)) << 20) + hcol;
    const int tr = tid >> 5;               // rows tr*8..+7 (n)
    const int tc = tid & 31;               // col-pairs: cols 64*j + 2*tc
    const int an = tid & 31;               // A loader: batch row
    const int aq = (tid >> 5) * 4;         // A loader: k quad

    // Cell constants
    const int cn = kc * 4 + (tid >> 5);    // batch row for cell
    const int ch = ht * 64 + (tid & 31) * 2;  // h pair for cell
    float cc0 = 0.0f, cc1 = 0.0f;          // cell state (registers)
    float hr0 = 0.0f, hr1 = 0.0f;          // hidden state (registers)
    const float* mrow = mask + cn * SL;

    __shared__ u64   As2[16][33];          // [k][n] duplicated {h,h}
    __shared__ float Bs[16][256];          // [k][col]

    for (int t = 0; t < SL; t++) {
        const int pos = dir ? (SL - 1 - t) : t;

        // Prefetch cell inputs (independent of this step's partials)
        float2 xpre[4];
#pragma unroll
        for (int g = 0; g < 4; ++g)
            xpre[g] = __ldcg((const float2*)&g_xh[
                ((((size_t)(dir * 4 + g) * SL + pos) * NB + cn) << 10) + ch]);
        const float m = mrow[pos];

        // ================= GEMM phase (pipelined) =================
        u64 acc[8][4];
#pragma unroll
        for (int i = 0; i < 8; i++)
#pragma unroll
            for (int j = 0; j < 4; j++) acc[i][j] = pk2(0.0f, 0.0f);

        int kb = kc * KCH;
        float4 hv = __ldcg((const float4*)&g_h[dir][an][kb + aq]);
        float4 wv[8];
#pragma unroll
        for (int r = 0; r < 8; ++r) {
            int lin = tid + r * 128;
            wv[r] = *(const float4*)(W + (size_t)(kb + (lin >> 6)) * HH +
                                     (lin & 63) * 4);
        }

        for (int it = 0; it < KCH / 16; ++it) {
            __syncthreads();               // prev-iter readers done
            As2[aq + 0][an] = pk2(hv.x, hv.x);
            As2[aq + 1][an] = pk2(hv.y, hv.y);
            As2[aq + 2][an] = pk2(hv.z, hv.z);
            As2[aq + 3][an] = pk2(hv.w, hv.w);
#pragma unroll
            for (int r = 0; r < 8; ++r) {
                int lin = tid + r * 128;
                *(float4*)&Bs[lin >> 6][(lin & 63) * 4] = wv[r];
            }
            __syncthreads();

            if (it < KCH / 16 - 1) {       // prefetch next chunk
                int kb2 = kc * KCH + (it + 1) * 16;
                hv = __ldcg((const float4*)&g_h[dir][an][kb2 + aq]);
#pragma unroll
                for (int r = 0; r < 8; ++r) {
                    int lin = tid + r * 128;
                    wv[r] = *(const float4*)(W + (size_t)(kb2 + (lin >> 6)) * HH +
                                             (lin & 63) * 4);
                }
            }

#pragma unroll
            for (int kk = 0; kk < 16; ++kk) {
                u64 a8[8], b4[4];
#pragma unroll
                for (int i = 0; i < 8; i++) a8[i] = As2[kk][tr * 8 + i];
#pragma unroll
                for (int j = 0; j < 4; j++)
                    b4[j] = *(const u64*)&Bs[kk][64 * j + 2 * tc];
#pragma unroll
                for (int i = 0; i < 8; i++)
#pragma unroll
                    for (int j = 0; j < 4; j++)
                        ffma2(acc[i][j], a8[i], b4[j]);
            }
        }

        // Write partials: P[n][col0 + 64j + 2tc]
        {
            float* P = &g_part[dir][kc][0][0];
#pragma unroll
            for (int i = 0; i < 8; i++) {
                int row = tr * 8 + i;
                size_t rb = (size_t)row * 4096 + col0 + 2 * tc;
#pragma unroll
                for (int j = 0; j < 4; j++) {
                    float lo, hi; upk2(acc[i][j], lo, hi);
                    *(float2*)&P[rb + 64 * j] = make_float2(lo, hi);
                }
            }
        }

        // ================= barrier: partials ready =================
        __threadfence();
        __syncthreads();
        if (tid == 0) {
            atomicAdd(&g_bar[0][t], 1);
            while (*(volatile int*)&g_bar[0][t] < NBLK) __nanosleep(64);
        }
        __syncthreads();

        // ================= cell phase =================
        {
            float2 pre[4] = {xpre[0], xpre[1], xpre[2], xpre[3]};
#pragma unroll
            for (int kcp = 0; kcp < NKC; ++kcp) {
#pragma unroll
                for (int g = 0; g < 4; ++g) {
                    float2 v = __ldcg((const float2*)
                        &g_part[dir][kcp][cn][(g << 10) + ch]);
                    pre[g].x += v.x; pre[g].y += v.y;
                }
            }

            float f0 = sigmf(pre[0].x), f1 = sigmf(pre[0].y);
            float i0 = sigmf(pre[1].x), i1 = sigmf(pre[1].y);
            float o0 = sigmf(pre[2].x), o1 = sigmf(pre[2].y);
            cc0 = f0 * cc0 + i0 * tanhf(pre[3].x);
            cc1 = f1 * cc1 + i1 * tanhf(pre[3].y);
            float hn0 = o0 * tanhf(cc0);
            float hn1 = o1 * tanhf(cc1);
            hr0 = (m == 0.0f) ? hr0 : hn0;
            hr1 = (m == 0.0f) ? hr1 : hn1;

            *(float2*)&g_h[dir][cn][ch] = make_float2(hr0, hr1);
            *(float2*)&out[(((size_t)cn * SL + pos) * 2 + dir) * HH + ch] =
                make_float2(hr0 * m, hr1 * m);
            if (t == SL - 1) {
                *(float2*)&out[(size_t)NB * SL * 2 * HH +
                               ((size_t)cn * 2 + dir) * HH + ch] =
                    make_float2(hr0, hr1);
            }
        }

        // ================= barrier: h ready =================
        __threadfence();
        __syncthreads();
        if (tid == 0) {
            atomicAdd(&g_bar[1][t], 1);
            while (*(volatile int*)&g_bar[1][t] < NBLK) __nanosleep(64);
        }
        __syncthreads();
    }
}

// ---------------------------------------------------------------------------
// Launch
// ---------------------------------------------------------------------------
extern "C" void kernel_launch(void* const* d_in, const int* in_sizes, int n_in,
                              void* d_out, int out_size) {
    const float* x    = (const float*)d_in[0];   // (32,256,1024)
    const float* mask = (const float*)d_in[1];   // (32,256)
    const float* wih  = (const float*)d_in[2];   // (8,1024,1024)
    const float* whh  = (const float*)d_in[3];   // (8,1024,1024)
    const float* bias = (const float*)d_in[4];   // (8,1,1024)
    float* out = (float*)d_out;

    zero_state_kernel<<<64, 256>>>();
    convert_x_kernel<<<1024, 256>>>(x);
    dim3 wgrid(32, 32, 8);
    convert_w_kernel<<<wgrid, dim3(32, 8)>>>(wih);

    dim3 ggrid(64, 16, 8);
    gemm_ih_mma_kernel<<<ggrid, 256>>>(bias);

    bilstm_persistent<<<NBLK, 128>>>(whh, mask, out);
}